// round 13
// baseline (speedup 1.0000x reference)
#include <cuda_runtime.h>
#include <math.h>

// ---------------- problem constants ----------------
#define IMG   256
#define PP    49           // patch pixels (7x7)
#define WN    37           // search window
#define INC   18
#define RPAD  21           // PATCH/2 + WN/2
#define HP    298          // IMG + 2*RPAD
#define PG    292          // patch-grid size = IMG + WN - 1
#define LTOT  (PG*PG)      // 85264
#define NC    4096         // total centers (64x64)
#define M1    18
#define M2    55
#define CENTER_OFF (INC*WN + INC)   // 684
#define SA    60           // row stride for A and GsT
#define GROWS 52           // GsT rows: 49 + pad for apply wedges
#define MAXCHK 217         // sweep chunks for M=55

// ---------------- device scratch ----------------
__device__ float g_pad_y[HP*HP];
__device__ float g_pad_x[HP*HP];
__device__ float g_den1[IMG*IMG];
__device__ int   g_idx1[NC*M1];   // flat grid index r*PG + c
__device__ int   g_idx2[NC*M2];
__device__ float g_xsum[PP*LTOT];
__device__ float g_wsum[LTOT];

__device__ __forceinline__ int tri_row(int t) {
    int i = (int)((sqrtf(8.0f*(float)t + 1.0f) - 1.0f)*0.5f);
    while ((i+1)*(i+2)/2 <= t) ++i;
    while (i*(i+1)/2 > t) --i;
    return i;
}

// ---------------- reflect pad + zero accumulators (fused) ----------------
__global__ void pad_zero_kernel(const float* __restrict__ src, int use_den1) {
    int t = blockIdx.x * blockDim.x + threadIdx.x;
    if (t < HP*HP) {
        int y = t / HP - RPAD, x = t % HP - RPAD;
        y = (y < 0) ? -y : ((y > IMG-1) ? 2*(IMG-1) - y : y);
        x = (x < 0) ? -x : ((x > IMG-1) ? 2*(IMG-1) - x : x);
        float v = use_den1 ? g_den1[y*IMG + x] : src[y*IMG + x];
        if (use_den1) g_pad_x[t] = v; else g_pad_y[t] = v;
    }
    const int ZT = PP*LTOT + LTOT;
    for (int z = t; z < ZT; z += gridDim.x*blockDim.x) {
        if (z < PP*LTOT) g_xsum[z] = 0.f; else g_wsum[z - PP*LTOT] = 0.f;
    }
}

// ---------------- block matching ----------------
// dist(t) = sum_{7x7} (win[o+d] - cp[d])^2; unique (dist,index) order.
// 370 tiles (37 rows x 10 col-groups of 4); rows per lane -> conflict-free.
// Center patch in SMEM (broadcast reads) to cut ~49 regs/thread -> higher occupancy.
// 4-pass radix select over 32-bit dist + tie cleanup on index (exact stable top_k set).
template<int M, bool USE_X>
__global__ __launch_bounds__(256) void bm_kernel() {
    __shared__ float win[43*43 + 16];
    __shared__ float cps[PP];
    __shared__ unsigned int hist[256];
    __shared__ unsigned int wsum[8];
    __shared__ unsigned int s_selbin, s_need, s_cnt, s_min;

    const float* pad = USE_X ? g_pad_x : g_pad_y;
    int* idx_out = (M == M1) ? g_idx1 : g_idx2;
    const int tid = threadIdx.x;
    const int ci = blockIdx.x >> 6, cj = blockIdx.x & 63;
    const int r0 = 4*ci, c0 = 4*cj;

    for (int t = tid; t < 43*43; t += 256)
        win[t] = pad[(r0 + t/43)*HP + (c0 + t%43)];
    if (tid < PP)   // center patch straight from global (no dependency on win)
        cps[tid] = pad[(r0 + INC + tid/7)*HP + (c0 + INC + tid%7)];
    if (tid == 0) s_cnt = 0;
    __syncthreads();

    unsigned int dk[8];
    int          ix[8];
#pragma unroll
    for (int q = 0; q < 8; ++q) { dk[q] = 0xFFFFFFFFu; ix[q] = 0xFFFF; }

    // 370 tiles; u%37 = row (consecutive per lane -> conflict-free window reads)
#pragma unroll
    for (int rq = 0; rq < 2; ++rq) {
        int u = tid + 256*rq;
        if (u < 370) {
            int o0 = u % 37;
            int c4 = (u / 37) * 4;
            float s0 = 0.f, s1 = 0.f, s2 = 0.f, s3 = 0.f;
#pragma unroll
            for (int di = 0; di < 7; ++di) {
                float w[10];
                const float* wr = &win[(o0 + di)*43 + c4];
#pragma unroll
                for (int x = 0; x < 10; ++x) w[x] = wr[x];
                const float* cr = &cps[di*7];
#pragma unroll
                for (int dj = 0; dj < 7; ++dj) {
                    float cv = cr[dj];
                    float d0 = w[dj]   - cv; s0 = fmaf(d0, d0, s0);
                    float d1 = w[dj+1] - cv; s1 = fmaf(d1, d1, s1);
                    float d2 = w[dj+2] - cv; s2 = fmaf(d2, d2, s2);
                    float d3 = w[dj+3] - cv; s3 = fmaf(d3, d3, s3);
                }
            }
            float sv[4] = {s0, s1, s2, s3};
#pragma unroll
            for (int cc = 0; cc < 4; ++cc) {
                int o1 = c4 + cc;
                if (o1 < WN) {
                    int t = o0*WN + o1;
                    unsigned int u32 = __float_as_uint(sv[cc]) | 0x80000000u;
                    if (t == CENTER_OFF) u32 = 0u;
                    dk[rq*4+cc] = u32;
                    ix[rq*4+cc] = t;
                }
            }
        }
    }

    // ---- 4-pass MSB radix select over 32-bit dist (parallel scan) ----
    unsigned int prefix = 0u;
    unsigned int need = M;
#pragma unroll 1
    for (int pass = 0; pass < 4; ++pass) {
        int shift = 24 - 8*pass;
        hist[tid] = 0;
        __syncthreads();
#pragma unroll
        for (int q = 0; q < 8; ++q) {
            if (ix[q] != 0xFFFF && (pass == 0 || (dk[q] >> (shift + 8)) == prefix))
                atomicAdd(&hist[(dk[q] >> shift) & 255u], 1u);
        }
        __syncthreads();
        unsigned int h = hist[tid];
        unsigned int v = h;
#pragma unroll
        for (int o = 1; o < 32; o <<= 1) {
            unsigned int n = __shfl_up_sync(0xffffffffu, v, o);
            if ((tid & 31) >= o) v += n;
        }
        if ((tid & 31) == 31) wsum[tid >> 5] = v;
        __syncthreads();
        if (tid < 8) {
            unsigned int w = wsum[tid];
            unsigned int x = w;
#pragma unroll
            for (int o = 1; o < 8; o <<= 1) {
                unsigned int n = __shfl_up_sync(0xffu, x, o);
                if (tid >= o) x += n;
            }
            wsum[tid] = x - w;   // exclusive
        }
        __syncthreads();
        unsigned int excl = v - h + wsum[tid >> 5];
        if (excl < need && need <= excl + h) {
            s_selbin = (unsigned int)tid;
            s_need   = need - excl;
        }
        __syncthreads();
        prefix = (prefix << 8) | s_selbin;
        need = s_need;
    }
    // prefix = D (dist of M-th smallest), need = r (rank among dist==D by index).

    // emit all dist < D (exactly M - r keys); collect ties dist == D.
    unsigned int tiemask = 0u;
#pragma unroll
    for (int q = 0; q < 8; ++q) {
        if (ix[q] != 0xFFFF) {
            if (dk[q] < prefix) {
                unsigned int pos = atomicAdd(&s_cnt, 1u);
                idx_out[blockIdx.x*M + pos] = (r0 + ix[q]/WN)*PG + (c0 + ix[q]%WN);
            } else if (dk[q] == prefix) {
                tiemask |= (1u << q);
            }
        }
    }
    // cleanup: r smallest indices among ties (usually r == 1)
#pragma unroll 1
    for (; need > 0; --need) {
        if (tid == 0) s_min = 0xFFFFFFFFu;
        __syncthreads();
        unsigned int tm = tiemask;
        while (tm) {
            int q = __ffs(tm) - 1;
            tm &= tm - 1;
            atomicMin(&s_min, (unsigned int)ix[q]);
        }
        __syncthreads();
        unsigned int mn = s_min;
        tm = tiemask;
        while (tm) {
            int q = __ffs(tm) - 1;
            tm &= tm - 1;
            if ((unsigned int)ix[q] == mn) {
                unsigned int pos = atomicAdd(&s_cnt, 1u);
                idx_out[blockIdx.x*M + pos] = (r0 + ix[q]/WN)*PG + (c0 + ix[q]%WN);
                tiemask &= ~(1u << q);
            }
        }
        __syncthreads();
    }
}

// ---------------- batched denoise: one block per group ----------------
// GsT[pixel*SA + patch]; A = G G^T (+cI); row-chunk register sweep -> a = -A^{-1};
// theta = I + c*a; Xh = theta*Y; w_k = 1/||theta_k||^2; scatter.
template<int M, int AR, int NCHK, int NCHUNK, int KSH, bool ADDC, bool GUIDE_X, bool RELOAD, int NT>
__global__ __launch_bounds__(NT) void denoise_kernel(const float* __restrict__ sigma_p) {
    __shared__ __align__(16) float GsT[GROWS*SA];
    __shared__ __align__(16) float A[AR*SA];
    __shared__ __align__(16) float rowbuf[2][64];
    __shared__ float wrow[64];
    __shared__ int   fidx[M2];
    __shared__ int   chunktab[MAXCHK];

    const int tid = threadIdx.x;
    const int* idx = (M == M1) ? g_idx1 : g_idx2;
    const float* gpad = GUIDE_X ? g_pad_x : g_pad_y;
    const float sg = *sigma_p;
    const float c  = (float)PP * sg * sg;
    constexpr int T = M*(M+1)/2;

    if (tid < M) fidx[tid] = idx[blockIdx.x*M + tid];
    // build sweep chunk table: row i -> ceil((i+1)/8) chunks of 8 columns
    if (tid < M) {
        int base = 0;
        for (int r = 0; r < tid; ++r) base += (r + 8) >> 3;
        int nc = (tid + 8) >> 3;
        for (int ch = 0; ch < nc; ++ch)
            chunktab[base + ch] = (tid << 8) | (ch << 3);
    }
    for (int t = tid; t < AR*SA + GROWS*SA; t += NT) {
        if (t < AR*SA) A[t] = 0.f; else GsT[t - AR*SA] = 0.f;
    }
    __syncthreads();

    // gather guide patches -> GsT[cc*SA + k]  (per-patch row-contiguous global reads)
    for (int t = tid; t < M*PP; t += NT) {
        int k = t / PP, cc = t % PP;
        int f = fidx[k]; int r = f / PG, q = f % PG;
        GsT[cc*SA + k] = gpad[(r + cc/7)*HP + q + cc%7];
    }
    __syncthreads();

    // ---- Gram: A = G G^T (+cI) ----
    if (M == M1) {
        for (int t = tid; t < T; t += NT) {
            int a0 = tri_row(t);
            int b0 = t - a0*(a0+1)/2;
            float s = 0.f;
#pragma unroll 7
            for (int cc = 0; cc < PP; ++cc)
                s = fmaf(GsT[cc*SA + a0], GsT[cc*SA + b0], s);
            if (ADDC && a0 == b0) s += c;
            A[a0*SA + b0] = s;
            A[b0*SA + a0] = s;
        }
    } else {
        if (tid < 105) {    // 4x4 tiles over 14x14 triangle grid
            int ti = tri_row(tid);
            int tj = tid - ti*(ti+1)/2;
            int i0 = 4*ti, j0 = 4*tj;
            float acc[4][4];
#pragma unroll
            for (int r = 0; r < 4; ++r)
#pragma unroll
                for (int q = 0; q < 4; ++q) acc[r][q] = 0.f;
#pragma unroll 7
            for (int cc = 0; cc < PP; ++cc) {
                float4 av = *(const float4*)&GsT[cc*SA + i0];
                float4 bv = *(const float4*)&GsT[cc*SA + j0];
                acc[0][0]=fmaf(av.x,bv.x,acc[0][0]); acc[0][1]=fmaf(av.x,bv.y,acc[0][1]);
                acc[0][2]=fmaf(av.x,bv.z,acc[0][2]); acc[0][3]=fmaf(av.x,bv.w,acc[0][3]);
                acc[1][0]=fmaf(av.y,bv.x,acc[1][0]); acc[1][1]=fmaf(av.y,bv.y,acc[1][1]);
                acc[1][2]=fmaf(av.y,bv.z,acc[1][2]); acc[1][3]=fmaf(av.y,bv.w,acc[1][3]);
                acc[2][0]=fmaf(av.z,bv.x,acc[2][0]); acc[2][1]=fmaf(av.z,bv.y,acc[2][1]);
                acc[2][2]=fmaf(av.z,bv.z,acc[2][2]); acc[2][3]=fmaf(av.z,bv.w,acc[2][3]);
                acc[3][0]=fmaf(av.w,bv.x,acc[3][0]); acc[3][1]=fmaf(av.w,bv.y,acc[3][1]);
                acc[3][2]=fmaf(av.w,bv.z,acc[3][2]); acc[3][3]=fmaf(av.w,bv.w,acc[3][3]);
            }
#pragma unroll
            for (int r = 0; r < 4; ++r)
#pragma unroll
                for (int q = 0; q < 4; ++q) {
                    float s = acc[r][q];
                    if (ADDC && (i0+r == j0+q)) s += c;
                    A[(i0+r)*SA + (j0+q)] = s;
                    A[(j0+q)*SA + (i0+r)] = s;
                }
        }
    }
    __syncthreads();

    // ---- chunk load: ea[8] = A[i][j0..j0+7]; init rowbuf[0] from column 0 ----
    const bool active = (tid < NCHK);
    int ii = 0, jj0 = 0;
    float ea[8];
    if (active) {
        int m = chunktab[tid];
        ii = m >> 8; jj0 = m & 255;
        float4 v0 = *(const float4*)&A[ii*SA + jj0];
        float4 v1 = *(const float4*)&A[ii*SA + jj0 + 4];
        ea[0]=v0.x; ea[1]=v0.y; ea[2]=v0.z; ea[3]=v0.w;
        ea[4]=v1.x; ea[5]=v1.y; ea[6]=v1.z; ea[7]=v1.w;
    }
    if (tid < M) rowbuf[0][tid] = A[tid*SA];   // row 0 by symmetry (column 0)

    // overlapped: reload Y into GsT (Gram done; sweep never reads GsT)
    if (RELOAD) {
        for (int t = tid; t < M*PP; t += NT) {
            int k = t / PP, cc = t % PP;
            int f = fidx[k]; int r = f / PG, q = f % PG;
            GsT[cc*SA + k] = g_pad_y[(r + cc/7)*HP + q + cc%7];
        }
    }
    __syncthreads();

    // ---- sweep: 1 barrier/iter; 4 LDS per chunk of 8 elements ----
#pragma unroll 1
    for (int k = 0; k < M; ++k) {
        const float* rk = rowbuf[k & 1];
        float* rn = rowbuf[(k + 1) & 1];
        if (active) {
            float pinv = 1.0f / rk[k];
            float4 r4a = *(const float4*)&rk[jj0];
            float4 r4b = *(const float4*)&rk[jj0 + 4];
            float rj[8] = {r4a.x, r4a.y, r4a.z, r4a.w, r4b.x, r4b.y, r4b.z, r4b.w};
            if (ii == k) {
#pragma unroll
                for (int q = 0; q < 8; ++q)
                    ea[q] = (jj0 + q == k) ? -pinv : rj[q] * pinv;
            } else {
                float f = rk[ii] * pinv;
#pragma unroll
                for (int q = 0; q < 8; ++q)
                    ea[q] = (jj0 + q == k) ? f : fmaf(-f, rj[q], ea[q]);
            }
            // publish updated row k+1 (rows below use symmetry via column k+1)
            if (ii == k + 1) {
                int nv = min(8, ii + 1 - jj0);
#pragma unroll
                for (int q = 0; q < 8; ++q)
                    if (q < nv) rn[jj0 + q] = ea[q];
            } else if (ii > k + 1 && (unsigned)(k + 1 - jj0) < 8u) {
                rn[ii] = ea[k + 1 - jj0];
            }
        }
        __syncthreads();
    }

    // ---- theta = I + c*a : write both halves (valid elements only) ----
    if (active) {
        int nv = min(8, ii + 1 - jj0);
#pragma unroll
        for (int q = 0; q < 8; ++q) {
            if (q < nv) {
                int j = jj0 + q;
                float th = fmaf(c, ea[q], (ii == j) ? 1.f : 0.f);
                A[ii*SA + j] = th;
                A[j*SA + ii] = th;
            }
        }
    }
    __syncthreads();

    // weights: 1/||theta_k||^2
    if (tid < M) {
        float s = 0.f;
#pragma unroll
        for (int g = 0; g < NCHUNK; ++g) {
            float4 v = *(const float4*)&A[tid*SA + 4*g];
            s = fmaf(v.x,v.x, fmaf(v.y,v.y, fmaf(v.z,v.z, fmaf(v.w,v.w, s))));
        }
        wrow[tid] = 1.f / s;
    }
    __syncthreads();

    // ---- apply: Xh[k][cc] = theta_k . Y[:,cc]; scatter Xh*w and w ----
    {
        int kslot = tid & ((1 << KSH) - 1);
        int wedge = tid >> KSH;           // 4 wedges x 13 pixel rows
        if (kslot < M) {
            float acc[13];
#pragma unroll
            for (int q = 0; q < 13; ++q) acc[q] = 0.f;
#pragma unroll
            for (int g = 0; g < NCHUNK; ++g) {
                float4 th4 = *(const float4*)&A[kslot*SA + 4*g];
                const float* yb = &GsT[(wedge*13)*SA + 4*g];
#pragma unroll
                for (int q = 0; q < 13; ++q) {
                    float4 y4 = *(const float4*)&yb[q*SA];
                    acc[q] = fmaf(th4.x, y4.x, acc[q]);
                    acc[q] = fmaf(th4.y, y4.y, acc[q]);
                    acc[q] = fmaf(th4.z, y4.z, acc[q]);
                    acc[q] = fmaf(th4.w, y4.w, acc[q]);
                }
            }
            float w = wrow[kslot];
            int f = fidx[kslot];
#pragma unroll
            for (int q = 0; q < 13; ++q) {
                int cc = wedge*13 + q;
                if (cc < PP) atomicAdd(&g_xsum[cc*LTOT + f], acc[q]*w);
            }
        }
    }
    if (tid < M)
        atomicAdd(&g_wsum[fidx[tid]], wrow[tid]);
}

// ---------------- fold + normalize + crop ----------------
__global__ void fold_kernel(float* __restrict__ out, int to_den1) {
    int t = blockIdx.x*blockDim.x + threadIdx.x;
    if (t >= IMG*IMG) return;
    int y = t >> 8, x = t & 255;
    float num = 0.f, den = 0.f;
#pragma unroll
    for (int i = 0; i < 7; ++i) {
        int base = (y + RPAD - i)*PG + (x + RPAD);
#pragma unroll
        for (int j = 0; j < 7; ++j) {
            int f = base - j;
            num += g_xsum[(i*7+j)*LTOT + f];
            den += g_wsum[f];
        }
    }
    float v = num / den;
    if (to_den1) g_den1[t] = v; else out[t] = v;
}

// ---------------- launch ----------------
extern "C" void kernel_launch(void* const* d_in, const int* in_sizes, int n_in,
                              void* d_out, int out_size) {
    const float* y   = (const float*)d_in[0];
    const float* sig = (const float*)d_in[1];
    float* out = (float*)d_out;

    // ---- pass 1 (p=7, m=18): 30 sweep chunks ----
    pad_zero_kernel<<<4096, 256>>>(y, 0);
    bm_kernel<M1, false><<<NC, 256>>>();
    denoise_kernel<M1, 20, 30, 5, 5, false, false, false, 128><<<NC, 128>>>(sig);
    fold_kernel<<<(IMG*IMG+255)/256, 256>>>(nullptr, 1);

    // ---- pass 2 (p=7, m=55): 217 sweep chunks ----
    pad_zero_kernel<<<4096, 256>>>(y, 1);
    bm_kernel<M2, true><<<NC, 256>>>();
    denoise_kernel<M2, 56, 217, 14, 6, true, true, true, 256><<<NC, 256>>>(sig);
    fold_kernel<<<(IMG*IMG+255)/256, 256>>>(out, 0);
}

// round 14
// speedup vs baseline: 1.0637x; 1.0637x over previous
#include <cuda_runtime.h>
#include <math.h>

// ---------------- problem constants ----------------
#define IMG   256
#define PP    49           // patch pixels (7x7)
#define WN    37           // search window
#define INC   18
#define RPAD  21           // PATCH/2 + WN/2
#define HP    298          // IMG + 2*RPAD
#define PG    292          // patch-grid size = IMG + WN - 1
#define LTOT  (PG*PG)      // 85264
#define NC    4096         // total centers (64x64)
#define M1    18
#define M2    55
#define CENTER_OFF (INC*WN + INC)   // 684
#define SA    60           // row stride for A and GsT
#define GROWS 52           // GsT rows: 49 + pad for apply wedges
#define MAXCHK 217         // sweep chunks for M=55
#define WSTR  47           // paired-window row stride (odd -> conflict-free)

// ---------------- device scratch ----------------
__device__ float g_pad_y[HP*HP];
__device__ float g_pad_x[HP*HP];
__device__ float g_den1[IMG*IMG];
__device__ int   g_idx1[NC*M1];   // flat grid index r*PG + c
__device__ int   g_idx2[NC*M2];
__device__ float g_xsum[PP*LTOT];
__device__ float g_wsum[LTOT];

__device__ __forceinline__ int tri_row(int t) {
    int i = (int)((sqrtf(8.0f*(float)t + 1.0f) - 1.0f)*0.5f);
    while ((i+1)*(i+2)/2 <= t) ++i;
    while (i*(i+1)/2 > t) --i;
    return i;
}

// ---------------- reflect pad + zero accumulators (fused) ----------------
__global__ void pad_zero_kernel(const float* __restrict__ src, int use_den1) {
    int t = blockIdx.x * blockDim.x + threadIdx.x;
    if (t < HP*HP) {
        int y = t / HP - RPAD, x = t % HP - RPAD;
        y = (y < 0) ? -y : ((y > IMG-1) ? 2*(IMG-1) - y : y);
        x = (x < 0) ? -x : ((x > IMG-1) ? 2*(IMG-1) - x : x);
        float v = use_den1 ? g_den1[y*IMG + x] : src[y*IMG + x];
        if (use_den1) g_pad_x[t] = v; else g_pad_y[t] = v;
    }
    const int ZT = PP*LTOT + LTOT;
    for (int z = t; z < ZT; z += gridDim.x*blockDim.x) {
        if (z < PP*LTOT) g_xsum[z] = 0.f; else g_wsum[z - PP*LTOT] = 0.f;
    }
}

// ---------------- block matching: one block per PAIR of adjacent centers ----------------
// Threads 0-127 own center A (cj), 128-255 own center B (cj+1); shared 43x47 window.
// dist(t) = sum_{7x7} (win[o+d] - cp[d])^2; unique (dist,index) order per center.
// One 4-pass radix select serves BOTH centers (two histograms, same barrier envelope);
// tie cleanup per center (exact stable top_k set).
template<int M, bool USE_X>
__global__ __launch_bounds__(256) void bm_kernel() {
    __shared__ float win[43*WSTR + 16];
    __shared__ unsigned int hist[2][256];
    __shared__ unsigned int wsumS[2][8];
    __shared__ unsigned int s_sel[2];
    __shared__ unsigned int s_cnt[2];
    __shared__ unsigned int s_min[2];

    const float* pad = USE_X ? g_pad_x : g_pad_y;
    int* idx_out = (M == M1) ? g_idx1 : g_idx2;
    const int tid = threadIdx.x;
    const int ci  = blockIdx.x >> 5;        // 0..63
    const int cjp = blockIdx.x & 31;        // pair index 0..31
    const int r0 = 4*ci, c0 = 8*cjp;        // window-union top-left (padded coords)
    const int half = tid >> 7;              // 0 = center A, 1 = center B
    const int lid7 = tid & 127;
    const int bcol = half*4;                // this center's column base in the window

    for (int t = tid; t < 43*WSTR; t += 256)
        win[t] = pad[(r0 + t/WSTR)*HP + (c0 + t%WSTR)];
    if (tid < 2) s_cnt[tid] = 0;
    __syncthreads();

    float cp[PP];
#pragma unroll
    for (int d = 0; d < PP; ++d) cp[d] = win[(INC + d/7)*WSTR + (bcol + INC + d%7)];

    unsigned int dk[12];
    int          ix[12];
#pragma unroll
    for (int q = 0; q < 12; ++q) { dk[q] = 0xFFFFFFFFu; ix[q] = 0xFFFF; }

    // 370 tiles per center on 128 threads (3 strided); rows per lane -> conflict-free
#pragma unroll
    for (int rq = 0; rq < 3; ++rq) {
        int u = lid7 + 128*rq;
        if (u < 370) {
            int o0 = u % 37;
            int c4 = (u / 37) * 4;
            float s0 = 0.f, s1 = 0.f, s2 = 0.f, s3 = 0.f;
#pragma unroll
            for (int di = 0; di < 7; ++di) {
                float w[10];
                const float* wr = &win[(o0 + di)*WSTR + bcol + c4];
#pragma unroll
                for (int x = 0; x < 10; ++x) w[x] = wr[x];
#pragma unroll
                for (int dj = 0; dj < 7; ++dj) {
                    float cv = cp[di*7 + dj];
                    float d0 = w[dj]   - cv; s0 = fmaf(d0, d0, s0);
                    float d1 = w[dj+1] - cv; s1 = fmaf(d1, d1, s1);
                    float d2 = w[dj+2] - cv; s2 = fmaf(d2, d2, s2);
                    float d3 = w[dj+3] - cv; s3 = fmaf(d3, d3, s3);
                }
            }
            float sv[4] = {s0, s1, s2, s3};
#pragma unroll
            for (int cc = 0; cc < 4; ++cc) {
                int o1 = c4 + cc;
                if (o1 < WN) {
                    int t = o0*WN + o1;
                    unsigned int u32 = __float_as_uint(sv[cc]) | 0x80000000u;
                    if (t == CENTER_OFF) u32 = 0u;
                    dk[rq*4+cc] = u32;
                    ix[rq*4+cc] = t;
                }
            }
        }
    }

    // ---- 4-pass MSB radix select over 32-bit dist, BOTH centers per pass ----
    unsigned int prefix[2] = {0u, 0u};
    unsigned int need[2]   = {M, M};
#pragma unroll 1
    for (int pass = 0; pass < 4; ++pass) {
        int shift = 24 - 8*pass;
        hist[0][tid] = 0;
        hist[1][tid] = 0;
        __syncthreads();
#pragma unroll
        for (int q = 0; q < 12; ++q) {
            if (ix[q] != 0xFFFF && (pass == 0 || (dk[q] >> (shift + 8)) == prefix[half]))
                atomicAdd(&hist[half][(dk[q] >> shift) & 255u], 1u);
        }
        __syncthreads();
        unsigned int h0 = hist[0][tid], h1 = hist[1][tid];
        unsigned int v0 = h0, v1 = h1;
#pragma unroll
        for (int o = 1; o < 32; o <<= 1) {
            unsigned int n0 = __shfl_up_sync(0xffffffffu, v0, o);
            unsigned int n1 = __shfl_up_sync(0xffffffffu, v1, o);
            if ((tid & 31) >= o) { v0 += n0; v1 += n1; }
        }
        if ((tid & 31) == 31) { wsumS[0][tid >> 5] = v0; wsumS[1][tid >> 5] = v1; }
        __syncthreads();
        if (tid < 8) {
            unsigned int w0 = wsumS[0][tid], w1 = wsumS[1][tid];
            unsigned int x0 = w0, x1 = w1;
#pragma unroll
            for (int o = 1; o < 8; o <<= 1) {
                unsigned int n0 = __shfl_up_sync(0xffu, x0, o);
                unsigned int n1 = __shfl_up_sync(0xffu, x1, o);
                if (tid >= o) { x0 += n0; x1 += n1; }
            }
            wsumS[0][tid] = x0 - w0;   // exclusive
            wsumS[1][tid] = x1 - w1;
        }
        __syncthreads();
        unsigned int e0 = v0 - h0 + wsumS[0][tid >> 5];
        unsigned int e1 = v1 - h1 + wsumS[1][tid >> 5];
        if (e0 < need[0] && need[0] <= e0 + h0)
            s_sel[0] = (((unsigned int)tid) << 16) | (need[0] - e0);
        if (e1 < need[1] && need[1] <= e1 + h1)
            s_sel[1] = (((unsigned int)tid) << 16) | (need[1] - e1);
        __syncthreads();
#pragma unroll
        for (int c = 0; c < 2; ++c) {
            unsigned int sv = s_sel[c];
            prefix[c] = (prefix[c] << 8) | (sv >> 16);
            need[c]   = sv & 0xffffu;
        }
    }
    // prefix[c] = D (dist of M-th smallest), need[c] = rank among dist==D by index.

    // emit all dist < D for own center; collect ties dist == D.
    const int cgbase = (ci*64 + 2*cjp + half)*M;    // this center's output base
    unsigned int tiemask = 0u;
#pragma unroll
    for (int q = 0; q < 12; ++q) {
        if (ix[q] != 0xFFFF) {
            if (dk[q] < prefix[half]) {
                unsigned int pos = atomicAdd(&s_cnt[half], 1u);
                idx_out[cgbase + pos] = (r0 + ix[q]/WN)*PG + (c0 + 4*half + ix[q]%WN);
            } else if (dk[q] == prefix[half]) {
                tiemask |= (1u << q);
            }
        }
    }
    // cleanup per center: r smallest indices among ties (usually r == 1)
#pragma unroll 1
    for (int c = 0; c < 2; ++c) {
#pragma unroll 1
        for (; need[c] > 0; --need[c]) {
            if (tid == 0) s_min[c] = 0xFFFFFFFFu;
            __syncthreads();
            if (half == c) {
                unsigned int tm = tiemask;
                while (tm) {
                    int q = __ffs(tm) - 1;
                    tm &= tm - 1;
                    atomicMin(&s_min[c], (unsigned int)ix[q]);
                }
            }
            __syncthreads();
            unsigned int mn = s_min[c];
            if (half == c) {
                unsigned int tm = tiemask;
                while (tm) {
                    int q = __ffs(tm) - 1;
                    tm &= tm - 1;
                    if ((unsigned int)ix[q] == mn) {
                        unsigned int pos = atomicAdd(&s_cnt[c], 1u);
                        idx_out[cgbase + pos] = (r0 + ix[q]/WN)*PG + (c0 + 4*half + ix[q]%WN);
                        tiemask &= ~(1u << q);
                    }
                }
            }
            __syncthreads();
        }
    }
}

// ---------------- batched denoise: one block per group ----------------
// GsT[pixel*SA + patch]; A = G G^T (+cI); row-chunk register sweep -> a = -A^{-1};
// theta = I + c*a; Xh = theta*Y; w_k = 1/||theta_k||^2; scatter.
template<int M, int AR, int NCHK, int NCHUNK, int KSH, bool ADDC, bool GUIDE_X, bool RELOAD, int NT>
__global__ __launch_bounds__(NT) void denoise_kernel(const float* __restrict__ sigma_p) {
    __shared__ __align__(16) float GsT[GROWS*SA];
    __shared__ __align__(16) float A[AR*SA];
    __shared__ __align__(16) float rowbuf[2][64];
    __shared__ float wrow[64];
    __shared__ int   fidx[M2];
    __shared__ int   chunktab[MAXCHK];

    const int tid = threadIdx.x;
    const int* idx = (M == M1) ? g_idx1 : g_idx2;
    const float* gpad = GUIDE_X ? g_pad_x : g_pad_y;
    const float sg = *sigma_p;
    const float c  = (float)PP * sg * sg;
    constexpr int T = M*(M+1)/2;

    if (tid < M) fidx[tid] = idx[blockIdx.x*M + tid];
    // build sweep chunk table: row i -> ceil((i+1)/8) chunks of 8 columns
    if (tid < M) {
        int base = 0;
        for (int r = 0; r < tid; ++r) base += (r + 8) >> 3;
        int nc = (tid + 8) >> 3;
        for (int ch = 0; ch < nc; ++ch)
            chunktab[base + ch] = (tid << 8) | (ch << 3);
    }
    for (int t = tid; t < AR*SA + GROWS*SA; t += NT) {
        if (t < AR*SA) A[t] = 0.f; else GsT[t - AR*SA] = 0.f;
    }
    __syncthreads();

    // gather guide patches -> GsT[cc*SA + k]  (per-patch row-contiguous global reads)
    for (int t = tid; t < M*PP; t += NT) {
        int k = t / PP, cc = t % PP;
        int f = fidx[k]; int r = f / PG, q = f % PG;
        GsT[cc*SA + k] = gpad[(r + cc/7)*HP + q + cc%7];
    }
    __syncthreads();

    // ---- Gram: A = G G^T (+cI) ----
    if (M == M1) {
        for (int t = tid; t < T; t += NT) {
            int a0 = tri_row(t);
            int b0 = t - a0*(a0+1)/2;
            float s = 0.f;
#pragma unroll 7
            for (int cc = 0; cc < PP; ++cc)
                s = fmaf(GsT[cc*SA + a0], GsT[cc*SA + b0], s);
            if (ADDC && a0 == b0) s += c;
            A[a0*SA + b0] = s;
            A[b0*SA + a0] = s;
        }
    } else {
        if (tid < 105) {    // 4x4 tiles over 14x14 triangle grid
            int ti = tri_row(tid);
            int tj = tid - ti*(ti+1)/2;
            int i0 = 4*ti, j0 = 4*tj;
            float acc[4][4];
#pragma unroll
            for (int r = 0; r < 4; ++r)
#pragma unroll
                for (int q = 0; q < 4; ++q) acc[r][q] = 0.f;
#pragma unroll 7
            for (int cc = 0; cc < PP; ++cc) {
                float4 av = *(const float4*)&GsT[cc*SA + i0];
                float4 bv = *(const float4*)&GsT[cc*SA + j0];
                acc[0][0]=fmaf(av.x,bv.x,acc[0][0]); acc[0][1]=fmaf(av.x,bv.y,acc[0][1]);
                acc[0][2]=fmaf(av.x,bv.z,acc[0][2]); acc[0][3]=fmaf(av.x,bv.w,acc[0][3]);
                acc[1][0]=fmaf(av.y,bv.x,acc[1][0]); acc[1][1]=fmaf(av.y,bv.y,acc[1][1]);
                acc[1][2]=fmaf(av.y,bv.z,acc[1][2]); acc[1][3]=fmaf(av.y,bv.w,acc[1][3]);
                acc[2][0]=fmaf(av.z,bv.x,acc[2][0]); acc[2][1]=fmaf(av.z,bv.y,acc[2][1]);
                acc[2][2]=fmaf(av.z,bv.z,acc[2][2]); acc[2][3]=fmaf(av.z,bv.w,acc[2][3]);
                acc[3][0]=fmaf(av.w,bv.x,acc[3][0]); acc[3][1]=fmaf(av.w,bv.y,acc[3][1]);
                acc[3][2]=fmaf(av.w,bv.z,acc[3][2]); acc[3][3]=fmaf(av.w,bv.w,acc[3][3]);
            }
#pragma unroll
            for (int r = 0; r < 4; ++r)
#pragma unroll
                for (int q = 0; q < 4; ++q) {
                    float s = acc[r][q];
                    if (ADDC && (i0+r == j0+q)) s += c;
                    A[(i0+r)*SA + (j0+q)] = s;
                    A[(j0+q)*SA + (i0+r)] = s;
                }
        }
    }
    __syncthreads();

    // ---- chunk load: ea[8] = A[i][j0..j0+7]; init rowbuf[0] from column 0 ----
    const bool active = (tid < NCHK);
    int ii = 0, jj0 = 0;
    float ea[8];
    if (active) {
        int m = chunktab[tid];
        ii = m >> 8; jj0 = m & 255;
        float4 v0 = *(const float4*)&A[ii*SA + jj0];
        float4 v1 = *(const float4*)&A[ii*SA + jj0 + 4];
        ea[0]=v0.x; ea[1]=v0.y; ea[2]=v0.z; ea[3]=v0.w;
        ea[4]=v1.x; ea[5]=v1.y; ea[6]=v1.z; ea[7]=v1.w;
    }
    if (tid < M) rowbuf[0][tid] = A[tid*SA];   // row 0 by symmetry (column 0)

    // overlapped: reload Y into GsT (Gram done; sweep never reads GsT)
    if (RELOAD) {
        for (int t = tid; t < M*PP; t += NT) {
            int k = t / PP, cc = t % PP;
            int f = fidx[k]; int r = f / PG, q = f % PG;
            GsT[cc*SA + k] = g_pad_y[(r + cc/7)*HP + q + cc%7];
        }
    }
    __syncthreads();

    // ---- sweep: 1 barrier/iter; 4 LDS per chunk of 8 elements ----
#pragma unroll 1
    for (int k = 0; k < M; ++k) {
        const float* rk = rowbuf[k & 1];
        float* rn = rowbuf[(k + 1) & 1];
        if (active) {
            float pinv = 1.0f / rk[k];
            float4 r4a = *(const float4*)&rk[jj0];
            float4 r4b = *(const float4*)&rk[jj0 + 4];
            float rj[8] = {r4a.x, r4a.y, r4a.z, r4a.w, r4b.x, r4b.y, r4b.z, r4b.w};
            if (ii == k) {
#pragma unroll
                for (int q = 0; q < 8; ++q)
                    ea[q] = (jj0 + q == k) ? -pinv : rj[q] * pinv;
            } else {
                float f = rk[ii] * pinv;
#pragma unroll
                for (int q = 0; q < 8; ++q)
                    ea[q] = (jj0 + q == k) ? f : fmaf(-f, rj[q], ea[q]);
            }
            // publish updated row k+1 (rows below use symmetry via column k+1)
            if (ii == k + 1) {
                int nv = min(8, ii + 1 - jj0);
#pragma unroll
                for (int q = 0; q < 8; ++q)
                    if (q < nv) rn[jj0 + q] = ea[q];
            } else if (ii > k + 1 && (unsigned)(k + 1 - jj0) < 8u) {
                rn[ii] = ea[k + 1 - jj0];
            }
        }
        __syncthreads();
    }

    // ---- theta = I + c*a : write both halves (valid elements only) ----
    if (active) {
        int nv = min(8, ii + 1 - jj0);
#pragma unroll
        for (int q = 0; q < 8; ++q) {
            if (q < nv) {
                int j = jj0 + q;
                float th = fmaf(c, ea[q], (ii == j) ? 1.f : 0.f);
                A[ii*SA + j] = th;
                A[j*SA + ii] = th;
            }
        }
    }
    __syncthreads();

    // weights: 1/||theta_k||^2
    if (tid < M) {
        float s = 0.f;
#pragma unroll
        for (int g = 0; g < NCHUNK; ++g) {
            float4 v = *(const float4*)&A[tid*SA + 4*g];
            s = fmaf(v.x,v.x, fmaf(v.y,v.y, fmaf(v.z,v.z, fmaf(v.w,v.w, s))));
        }
        wrow[tid] = 1.f / s;
    }
    __syncthreads();

    // ---- apply: Xh[k][cc] = theta_k . Y[:,cc]; scatter Xh*w and w ----
    {
        int kslot = tid & ((1 << KSH) - 1);
        int wedge = tid >> KSH;           // 4 wedges x 13 pixel rows
        if (kslot < M) {
            float acc[13];
#pragma unroll
            for (int q = 0; q < 13; ++q) acc[q] = 0.f;
#pragma unroll
            for (int g = 0; g < NCHUNK; ++g) {
                float4 th4 = *(const float4*)&A[kslot*SA + 4*g];
                const float* yb = &GsT[(wedge*13)*SA + 4*g];
#pragma unroll
                for (int q = 0; q < 13; ++q) {
                    float4 y4 = *(const float4*)&yb[q*SA];
                    acc[q] = fmaf(th4.x, y4.x, acc[q]);
                    acc[q] = fmaf(th4.y, y4.y, acc[q]);
                    acc[q] = fmaf(th4.z, y4.z, acc[q]);
                    acc[q] = fmaf(th4.w, y4.w, acc[q]);
                }
            }
            float w = wrow[kslot];
            int f = fidx[kslot];
#pragma unroll
            for (int q = 0; q < 13; ++q) {
                int cc = wedge*13 + q;
                if (cc < PP) atomicAdd(&g_xsum[cc*LTOT + f], acc[q]*w);
            }
        }
    }
    if (tid < M)
        atomicAdd(&g_wsum[fidx[tid]], wrow[tid]);
}

// ---------------- fold + normalize + crop ----------------
__global__ void fold_kernel(float* __restrict__ out, int to_den1) {
    int t = blockIdx.x*blockDim.x + threadIdx.x;
    if (t >= IMG*IMG) return;
    int y = t >> 8, x = t & 255;
    float num = 0.f, den = 0.f;
#pragma unroll
    for (int i = 0; i < 7; ++i) {
        int base = (y + RPAD - i)*PG + (x + RPAD);
#pragma unroll
        for (int j = 0; j < 7; ++j) {
            int f = base - j;
            num += g_xsum[(i*7+j)*LTOT + f];
            den += g_wsum[f];
        }
    }
    float v = num / den;
    if (to_den1) g_den1[t] = v; else out[t] = v;
}

// ---------------- launch ----------------
extern "C" void kernel_launch(void* const* d_in, const int* in_sizes, int n_in,
                              void* d_out, int out_size) {
    const float* y   = (const float*)d_in[0];
    const float* sig = (const float*)d_in[1];
    float* out = (float*)d_out;

    // ---- pass 1 (p=7, m=18): 30 sweep chunks ----
    pad_zero_kernel<<<4096, 256>>>(y, 0);
    bm_kernel<M1, false><<<NC/2, 256>>>();
    denoise_kernel<M1, 20, 30, 5, 5, false, false, false, 128><<<NC, 128>>>(sig);
    fold_kernel<<<(IMG*IMG+255)/256, 256>>>(nullptr, 1);

    // ---- pass 2 (p=7, m=55): 217 sweep chunks ----
    pad_zero_kernel<<<4096, 256>>>(y, 1);
    bm_kernel<M2, true><<<NC/2, 256>>>();
    denoise_kernel<M2, 56, 217, 14, 6, true, true, true, 256><<<NC, 256>>>(sig);
    fold_kernel<<<(IMG*IMG+255)/256, 256>>>(out, 0);
}